// round 9
// baseline (speedup 1.0000x reference)
#include <cuda_runtime.h>
#include <cstdint>

#define B_NO   8
#define T_DATA 5000
#define E_NO   2000
#define SUB_NO 20
#define HID_NO 10
#define SH_NO  200
#define T_NO   50
#define NCH    1600

#define PCH 10
#define NCHUNKS 500

// Parity-split named barriers: a named barrier is a raw arrival counter, so each
// barrier may receive at most ONE arrival per participant per completion.
// ids: 1=BARP_even, 2=BARP_odd (P[k] ready), 3=BARY_even, 4=BARY_odd (y[k] ready)
#define FENCE_CTA()    asm volatile("membar.cta;" ::: "memory")
#define BAR_ARRIVE(id) asm volatile("bar.arrive %0, %1;" :: "r"(id), "r"(128) : "memory")
#define BAR_SYNCN(id)  asm volatile("bar.sync %0, %1;"   :: "r"(id), "r"(128) : "memory")

__device__ float g_CT[E_NO * SUB_NO];
__device__ float g_syn[B_NO * SUB_NO * T_DATA];
__device__ float g_conv[B_NO * SH_NO * (size_t)T_DATA];
__device__ float g_ybuf[B_NO * SH_NO * (size_t)T_DATA];

__device__ __forceinline__ unsigned long long pk2(float x, float y) {
    unsigned long long r;
    asm("mov.b64 %0, {%1, %2};" : "=l"(r) : "f"(x), "f"(y));
    return r;
}
__device__ __forceinline__ unsigned long long ffma2(unsigned long long a,
                                                    unsigned long long b,
                                                    unsigned long long c) {
    unsigned long long d;
    asm("fma.rn.f32x2 %0, %1, %2, %3;" : "=l"(d) : "l"(a), "l"(b), "l"(c));
    return d;
}
__device__ __forceinline__ unsigned long long add2(unsigned long long a,
                                                   unsigned long long b) {
    unsigned long long d;
    asm("add.rn.f32x2 %0, %1, %2;" : "=l"(d) : "l"(a), "l"(b));
    return d;
}
__device__ __forceinline__ float2 upk2(unsigned long long v) {
    float2 f;
    asm("mov.b64 {%0, %1}, %2;" : "=f"(f.x), "=f"(f.y) : "l"(v));
    return f;
}
__device__ __forceinline__ float tanh_hw(float x) {
    float y;
    asm("tanh.approx.f32 %0, %1;" : "=f"(y) : "f"(x));
    return y;
}

// ---------- 1. prep ----------
__global__ void prep_kernel(const float* __restrict__ C, const float* __restrict__ Esc) {
    int i = blockIdx.x * 256 + threadIdx.x;
    if (i >= E_NO * SUB_NO) return;
    int e = i / SUB_NO, s = i % SUB_NO;
    g_CT[i] = C[s * E_NO + e] * expf(Esc[e]);
}

// ---------- 2. GEMM (double-buffered, reg-prefetch) ----------
#define ETILE 16
#define GROWS 128
#define GTHR  64
#define NTILE (E_NO / ETILE)

__global__ void __launch_bounds__(GTHR) gemm_kernel(const float* __restrict__ S_e) {
    __shared__ float sS[2][GROWS * 17];
    __shared__ float sC[2][ETILE * 20];
    const int b = blockIdx.y;
    const int t0 = blockIdx.x * GROWS;
    const int tid = threadIdx.x;
    const float* Sb = S_e + (size_t)b * T_DATA * E_NO;

    unsigned long long acc0[10], acc1[10];
#pragma unroll
    for (int s = 0; s < 10; s++) { acc0[s] = 0ull; acc1[s] = 0ull; }

    float4 pf[8];
    float pc[5];

#define LDG_TILE(E0)                                                        \
    {                                                                       \
        _Pragma("unroll")                                                   \
        for (int kk = 0; kk < 8; kk++) {                                    \
            int q = tid + kk * GTHR;                                        \
            int r = q >> 2, c4 = q & 3;                                     \
            int t = t0 + r;                                                 \
            pf[kk] = (t < T_DATA)                                           \
                ? *(const float4*)(Sb + (size_t)t * E_NO + (E0) + c4 * 4)   \
                : make_float4(0.f, 0.f, 0.f, 0.f);                          \
        }                                                                   \
        _Pragma("unroll")                                                   \
        for (int m = 0; m < 5; m++) pc[m] = g_CT[(E0) * 20 + tid * 5 + m];  \
    }

#define STS_TILE(BUF)                                                       \
    {                                                                       \
        _Pragma("unroll")                                                   \
        for (int kk = 0; kk < 8; kk++) {                                    \
            int q = tid + kk * GTHR;                                        \
            int r = q >> 2, c4 = q & 3;                                     \
            float* d = &sS[BUF][r * 17 + c4 * 4];                           \
            d[0] = pf[kk].x; d[1] = pf[kk].y;                               \
            d[2] = pf[kk].z; d[3] = pf[kk].w;                               \
        }                                                                   \
        _Pragma("unroll")                                                   \
        for (int m = 0; m < 5; m++) sC[BUF][tid * 5 + m] = pc[m];           \
    }

    LDG_TILE(0);
    STS_TILE(0);
    LDG_TILE(ETILE);
    __syncthreads();

    for (int it = 0; it < NTILE; it++) {
        const int cur = it & 1;
#pragma unroll
        for (int j = 0; j < ETILE; j++) {
            unsigned long long cp[10];
#pragma unroll
            for (int s = 0; s < 10; s++)
                cp[s] = *(const unsigned long long*)&sC[cur][j * 20 + 2 * s];
            float v0 = sS[cur][tid * 17 + j];
            float v1 = sS[cur][(tid + GTHR) * 17 + j];
            unsigned long long v0p = pk2(v0, v0), v1p = pk2(v1, v1);
#pragma unroll
            for (int s = 0; s < 10; s++) {
                acc0[s] = ffma2(v0p, cp[s], acc0[s]);
                acc1[s] = ffma2(v1p, cp[s], acc1[s]);
            }
        }
        if (it < NTILE - 1) {
            STS_TILE(cur ^ 1);
            if (it < NTILE - 2) LDG_TILE((it + 2) * ETILE);
            __syncthreads();
        }
    }

    int ta = t0 + tid;
    if (ta < T_DATA) {
#pragma unroll
        for (int s = 0; s < 10; s++) {
            float2 f = upk2(acc0[s]);
            g_syn[((size_t)b * SUB_NO + 2 * s)     * T_DATA + ta] = f.x;
            g_syn[((size_t)b * SUB_NO + 2 * s + 1) * T_DATA + ta] = f.y;
        }
    }
    int tb = t0 + GTHR + tid;
    if (tb < T_DATA) {
#pragma unroll
        for (int s = 0; s < 10; s++) {
            float2 f = upk2(acc1[s]);
            g_syn[((size_t)b * SUB_NO + 2 * s)     * T_DATA + tb] = f.x;
            g_syn[((size_t)b * SUB_NO + 2 * s + 1) * T_DATA + tb] = f.y;
        }
    }
}

// ---------- 3. depthwise causal conv ----------
__global__ void __launch_bounds__(256) conv_kernel(const float* __restrict__ W1) {
    const int bs = blockIdx.x;
    const int b = bs / SUB_NO, s = bs % SUB_NO;
    __shared__ float ss[T_NO - 1 + T_DATA];
    const int tid = threadIdx.x;

    for (int i = tid; i < T_NO - 1; i += 256) ss[i] = 0.0f;
    const float* sp = g_syn + ((size_t)b * SUB_NO + s) * T_DATA;
    for (int i = tid; i < T_DATA; i += 256) ss[T_NO - 1 + i] = sp[i];
    __syncthreads();

    for (int h = 0; h < HID_NO; h++) {
        const int c = s * HID_NO + h;
        float w[T_NO];
#pragma unroll
        for (int i = 0; i < T_NO; i++) w[i] = __ldg(&W1[c * T_NO + i]);
        float* cp = g_conv + ((size_t)(b * SH_NO + c)) * T_DATA;
        for (int t = tid; t < T_DATA; t += 256) {
            float acc = 0.0f;
#pragma unroll
            for (int tau = 0; tau < T_NO; tau++)
                acc = fmaf(ss[T_NO - 1 + t - tau], w[tau], acc);
            cp[t] = acc;
        }
    }
}

// ---------- 4. recurrence: decoupled 4-warp pipeline, parity-split barriers ----------
// W0(A): taps 1..19 serial; W1: 20..29 + conv; W2: 30..39 + stores; W3: 40..50.
template<int TB0, int NT, int WD, int MODE>
__device__ __forceinline__ void run_helper(
    int lane, int ch, int c,
    const float* __restrict__ Wh, const float* __restrict__ b1,
    const float* __restrict__ W2l,
    unsigned long long (*s_y)[32][7], unsigned long long (*sp)[32][7])
{
    float w[NT];
#pragma unroll
    for (int u = 0; u < NT; u++) w[u] = __ldg(&Wh[c * T_NO + TB0 + u - 1]);
    const float bias = (MODE == 1) ? b1[c] : 0.0f;
    const float ew2  = (MODE == 2) ? expf(W2l[c]) : 0.0f;
    const float* cv = g_conv + (size_t)ch * T_DATA;
    float* yo = g_ybuf + (size_t)ch * T_DATA;

    float yw[WD];
#pragma unroll
    for (int i = 0; i < WD; i++) yw[i] = 0.0f;

    float cn[10];
    // prologue: P[0] -> BARP_even(1), P[1] -> BARP_odd(2)
#pragma unroll
    for (int pj = 0; pj < 2; pj++) {
        float* pr = (float*)&sp[pj][lane][0];
        if (MODE == 1) {
#pragma unroll
            for (int j = 0; j < 10; j += 2) {
                float2 t = *(const float2*)(cv + pj * PCH + j);
                pr[j] = t.x + bias; pr[j + 1] = t.y + bias;
            }
        } else {
#pragma unroll
            for (int j = 0; j < 10; j++) pr[j] = 0.0f;
        }
        FENCE_CTA();
        BAR_ARRIVE(1 + pj);
    }
    if (MODE == 1) {
#pragma unroll
        for (int j = 0; j < 10; j += 2) {
            float2 t = *(const float2*)(cv + 2 * PCH + j);
            cn[j] = t.x; cn[j + 1] = t.y;
        }
    }

    for (int j = 2; j < NCHUNKS; j++) {
        BAR_SYNCN(3 + (j & 1));          // y[j-2] ready (parity (j-2)&1 == j&1)
        float yn[10];
        {
            const unsigned long long* yr = &s_y[j & 1][lane][0];
#pragma unroll
            for (int q = 0; q < 5; q++) {
                float2 t = upk2(yr[q]);
                yn[2 * q] = t.x; yn[2 * q + 1] = t.y;
            }
        }
        if (MODE == 2) {
            float* yob = yo + (size_t)(j - 2) * PCH;
#pragma unroll
            for (int q = 0; q < 5; q++)
                *(float2*)(yob + 2 * q) =
                    make_float2(ew2 * yn[2 * q], ew2 * yn[2 * q + 1]);
        }
#pragma unroll
        for (int i = 0; i < WD - 10; i++) yw[i] = yw[i + 10];
#pragma unroll
        for (int jj = 0; jj < 10; jj++) yw[WD - 10 + jj] = yn[jj];

        float part[10];
        if (MODE == 1) {
#pragma unroll
            for (int jj = 0; jj < 10; jj++) part[jj] = cn[jj] + bias;
        } else {
#pragma unroll
            for (int jj = 0; jj < 10; jj++) part[jj] = 0.0f;
        }
#pragma unroll
        for (int jj = 0; jj < 10; jj++)
#pragma unroll
            for (int u = 0; u < NT; u++)
                part[jj] = fmaf(yw[WD + 10 + jj - TB0 - u], w[u], part[jj]);

        float* pw = (float*)&sp[j & 1][lane][0];
#pragma unroll
        for (int jj = 0; jj < 10; jj++) pw[jj] = part[jj];
        FENCE_CTA();
        BAR_ARRIVE(1 + (j & 1));         // P[j] ready

        if (MODE == 1) {                 // prefetch conv chunk j+1
            int nj = (j + 1 < NCHUNKS) ? (j + 1) : (NCHUNKS - 1);
#pragma unroll
            for (int jj = 0; jj < 10; jj += 2) {
                float2 t = *(const float2*)(cv + nj * PCH + jj);
                cn[jj] = t.x; cn[jj + 1] = t.y;
            }
        }
    }
    // tail: y[498] (even -> id 3), y[499] (odd -> id 4)
    BAR_SYNCN(3);
    if (MODE == 2) {
        const unsigned long long* yr = &s_y[(NCHUNKS - 2) & 1][lane][0];
        float* yob = yo + (size_t)(NCHUNKS - 2) * PCH;
#pragma unroll
        for (int q = 0; q < 5; q++) {
            float2 t = upk2(yr[q]);
            *(float2*)(yob + 2 * q) = make_float2(ew2 * t.x, ew2 * t.y);
        }
    }
    BAR_SYNCN(4);
    if (MODE == 2) {
        const unsigned long long* yr = &s_y[(NCHUNKS - 1) & 1][lane][0];
        float* yob = yo + (size_t)(NCHUNKS - 1) * PCH;
#pragma unroll
        for (int q = 0; q < 5; q++) {
            float2 t = upk2(yr[q]);
            *(float2*)(yob + 2 * q) = make_float2(ew2 * t.x, ew2 * t.y);
        }
    }
}

__global__ void __launch_bounds__(128, 1) recur_kernel(const float* __restrict__ Wh,
                                                       const float* __restrict__ b1,
                                                       const float* __restrict__ W2l) {
    __shared__ unsigned long long s_y[2][32][7];
    __shared__ unsigned long long s_p1[2][32][7];
    __shared__ unsigned long long s_p2[2][32][7];
    __shared__ unsigned long long s_p3[2][32][7];

    const int lane = threadIdx.x & 31;
    const int warp = threadIdx.x >> 5;
    const int ch = blockIdx.x * 32 + lane;
    const int c = ch % SH_NO;

    if (warp == 0) {
        float w[21];
#pragma unroll
        for (int i = 0; i < 19; i++) w[i] = __ldg(&Wh[c * T_NO + i]);
        w[19] = 0.0f; w[20] = 0.0f;
        unsigned long long wp0[10], wp1[10];
#pragma unroll
        for (int i = 0; i < 10; i++) {
            wp0[i] = pk2(w[2 * i], w[2 * i + 1]);
            wp1[i] = pk2(w[2 * i + 1], w[2 * i + 2]);
        }

        unsigned long long A2[15];
#pragma unroll
        for (int m = 0; m < 15; m++) A2[m] = 0ull;

        for (int k = 0; k < NCHUNKS; k++) {
            BAR_SYNCN(1 + (k & 1));      // P[k] ready (all 3 helpers arrived)
            const unsigned long long* pp1 = &s_p1[k & 1][lane][0];
            const unsigned long long* pp2 = &s_p2[k & 1][lane][0];
            const unsigned long long* pp3 = &s_p3[k & 1][lane][0];
#pragma unroll
            for (int m = 0; m < 5; m++)
                A2[m] = add2(A2[m], add2(add2(pp1[m], pp2[m]), pp3[m]));

            unsigned long long* yrow = &s_y[k & 1][lane][0];
#pragma unroll
            for (int pp = 0; pp < 5; pp++) {
                float2 a = upk2(A2[pp]);
                float y0 = tanh_hw(a.x);
                float v1 = fmaf(y0, w[0], a.y);
                float y1 = tanh_hw(v1);
                yrow[pp] = pk2(y0, y1);
                unsigned long long yy0 = pk2(y0, y0);
                unsigned long long yy1 = pk2(y1, y1);
#pragma unroll
                for (int i = 0; i < 10; i++)
                    A2[pp + 1 + i] = ffma2(yy0, wp1[i],
                                     ffma2(yy1, wp0[i], A2[pp + 1 + i]));
            }
            FENCE_CTA();
            BAR_ARRIVE(3 + (k & 1));     // y[k] ready
#pragma unroll
            for (int m = 0; m < 10; m++) A2[m] = A2[m + 5];
#pragma unroll
            for (int m = 10; m < 15; m++) A2[m] = 0ull;
        }
    } else if (warp == 1) {
        run_helper<20, 10, 19, 1>(lane, ch, c, Wh, b1, W2l, s_y, s_p1);
    } else if (warp == 2) {
        run_helper<30, 10, 29, 2>(lane, ch, c, Wh, b1, W2l, s_y, s_p2);
    } else {
        run_helper<40, 11, 40, 0>(lane, ch, c, Wh, b1, W2l, s_y, s_p3);
    }
}

// ---------- 5. reduce ----------
__global__ void __launch_bounds__(256) reduce_kernel(const float* __restrict__ V_o,
                                                     float* __restrict__ out) {
    int idx = blockIdx.x * 256 + threadIdx.x;
    if (idx >= B_NO * T_DATA) return;
    int b = idx / T_DATA, t = idx % T_DATA;
    const float* p = g_ybuf + (size_t)b * SH_NO * T_DATA + t;
    float a = V_o[0];
#pragma unroll 10
    for (int c = 0; c < SH_NO; c++) a += p[(size_t)c * T_DATA];
    out[idx] = a;
}

extern "C" void kernel_launch(void* const* d_in, const int* in_sizes, int n_in,
                              void* d_out, int out_size) {
    const float* S_e     = (const float*)d_in[0];
    const float* C_syn_e = (const float*)d_in[2];
    const float* E_scale = (const float*)d_in[4];
    const float* W1      = (const float*)d_in[6];
    const float* W2      = (const float*)d_in[7];
    const float* b1      = (const float*)d_in[8];
    const float* Wh      = (const float*)d_in[9];
    const float* V_o     = (const float*)d_in[11];
    float* out = (float*)d_out;

    prep_kernel<<<(E_NO * SUB_NO + 255) / 256, 256>>>(C_syn_e, E_scale);
    dim3 gg((T_DATA + GROWS - 1) / GROWS, B_NO);
    gemm_kernel<<<gg, GTHR>>>(S_e);
    conv_kernel<<<B_NO * SUB_NO, 256>>>(W1);
    recur_kernel<<<NCH / 32, 128>>>(Wh, b1, W2);
    reduce_kernel<<<(B_NO * T_DATA + 255) / 256, 256>>>(V_o, out);
}

// round 10
// speedup vs baseline: 1.0828x; 1.0828x over previous
#include <cuda_runtime.h>
#include <cstdint>

#define B_NO   8
#define T_DATA 5000
#define E_NO   2000
#define SUB_NO 20
#define HID_NO 10
#define SH_NO  200
#define T_NO   50
#define NCH    1600

#define PCH 10
#define NCHUNKS 500

__device__ float g_CT[E_NO * SUB_NO];
__device__ float g_syn[B_NO * SUB_NO * T_DATA];
__device__ float g_conv[B_NO * SH_NO * (size_t)T_DATA];
__device__ float g_ybuf[B_NO * SH_NO * (size_t)T_DATA];

__device__ __forceinline__ unsigned long long pk2(float x, float y) {
    unsigned long long r;
    asm("mov.b64 %0, {%1, %2};" : "=l"(r) : "f"(x), "f"(y));
    return r;
}
__device__ __forceinline__ unsigned long long ffma2(unsigned long long a,
                                                    unsigned long long b,
                                                    unsigned long long c) {
    unsigned long long d;
    asm("fma.rn.f32x2 %0, %1, %2, %3;" : "=l"(d) : "l"(a), "l"(b), "l"(c));
    return d;
}
__device__ __forceinline__ unsigned long long add2(unsigned long long a,
                                                   unsigned long long b) {
    unsigned long long d;
    asm("add.rn.f32x2 %0, %1, %2;" : "=l"(d) : "l"(a), "l"(b));
    return d;
}
__device__ __forceinline__ float2 upk2(unsigned long long v) {
    float2 f;
    asm("mov.b64 {%0, %1}, %2;" : "=f"(f.x), "=f"(f.y) : "l"(v));
    return f;
}
__device__ __forceinline__ float tanh_hw(float x) {
    float y;
    asm("tanh.approx.f32 %0, %1;" : "=f"(y) : "f"(x));
    return y;
}

// ---------- 1. prep ----------
__global__ void prep_kernel(const float* __restrict__ C, const float* __restrict__ Esc) {
    int i = blockIdx.x * 256 + threadIdx.x;
    if (i >= E_NO * SUB_NO) return;
    int e = i / SUB_NO, s = i % SUB_NO;
    g_CT[i] = C[s * E_NO + e] * expf(Esc[e]);
}

// ---------- 2. GEMM (double-buffered, 1 row/thread, 2+ warps/SMSP) ----------
#define ETILE 16
#define GROWS 128
#define GTHR  128
#define NTILE (E_NO / ETILE)

__global__ void __launch_bounds__(GTHR) gemm_kernel(const float* __restrict__ S_e) {
    __shared__ float sS[2][GROWS * 17];
    __shared__ float sC[2][ETILE * 20];
    const int b = blockIdx.y;
    const int t0 = blockIdx.x * GROWS;
    const int tid = threadIdx.x;
    const float* Sb = S_e + (size_t)b * T_DATA * E_NO;

    unsigned long long acc0[10];
#pragma unroll
    for (int s = 0; s < 10; s++) acc0[s] = 0ull;

    float4 pf[4];
    float pc[5];

#define LDG_TILE(E0)                                                        \
    {                                                                       \
        _Pragma("unroll")                                                   \
        for (int kk = 0; kk < 4; kk++) {                                    \
            int q = tid + kk * GTHR;                                        \
            int r = q >> 2, c4 = q & 3;                                     \
            int t = t0 + r;                                                 \
            pf[kk] = (t < T_DATA)                                           \
                ? *(const float4*)(Sb + (size_t)t * E_NO + (E0) + c4 * 4)   \
                : make_float4(0.f, 0.f, 0.f, 0.f);                          \
        }                                                                   \
        if (tid < 64) {                                                     \
            _Pragma("unroll")                                               \
            for (int m = 0; m < 5; m++)                                     \
                pc[m] = g_CT[(E0) * 20 + tid * 5 + m];                      \
        }                                                                   \
    }

#define STS_TILE(BUF)                                                       \
    {                                                                       \
        _Pragma("unroll")                                                   \
        for (int kk = 0; kk < 4; kk++) {                                    \
            int q = tid + kk * GTHR;                                        \
            int r = q >> 2, c4 = q & 3;                                     \
            float* d = &sS[BUF][r * 17 + c4 * 4];                           \
            d[0] = pf[kk].x; d[1] = pf[kk].y;                               \
            d[2] = pf[kk].z; d[3] = pf[kk].w;                               \
        }                                                                   \
        if (tid < 64) {                                                     \
            _Pragma("unroll")                                               \
            for (int m = 0; m < 5; m++) sC[BUF][tid * 5 + m] = pc[m];       \
        }                                                                   \
    }

    LDG_TILE(0);
    STS_TILE(0);
    LDG_TILE(ETILE);
    __syncthreads();

    for (int it = 0; it < NTILE; it++) {
        const int cur = it & 1;
#pragma unroll
        for (int j = 0; j < ETILE; j++) {
            unsigned long long cp[10];
#pragma unroll
            for (int s = 0; s < 10; s++)
                cp[s] = *(const unsigned long long*)&sC[cur][j * 20 + 2 * s];
            float v0 = sS[cur][tid * 17 + j];
            unsigned long long v0p = pk2(v0, v0);
#pragma unroll
            for (int s = 0; s < 10; s++)
                acc0[s] = ffma2(v0p, cp[s], acc0[s]);
        }
        if (it < NTILE - 1) {
            STS_TILE(cur ^ 1);
            if (it < NTILE - 2) LDG_TILE((it + 2) * ETILE);
            __syncthreads();
        }
    }

    int ta = t0 + tid;
    if (ta < T_DATA) {
#pragma unroll
        for (int s = 0; s < 10; s++) {
            float2 f = upk2(acc0[s]);
            g_syn[((size_t)b * SUB_NO + 2 * s)     * T_DATA + ta] = f.x;
            g_syn[((size_t)b * SUB_NO + 2 * s + 1) * T_DATA + ta] = f.y;
        }
    }
}

// ---------- 3. depthwise causal conv ----------
__global__ void __launch_bounds__(256) conv_kernel(const float* __restrict__ W1) {
    const int bs = blockIdx.x;
    const int b = bs / SUB_NO, s = bs % SUB_NO;
    __shared__ float ss[T_NO - 1 + T_DATA];
    const int tid = threadIdx.x;

    for (int i = tid; i < T_NO - 1; i += 256) ss[i] = 0.0f;
    const float* sp = g_syn + ((size_t)b * SUB_NO + s) * T_DATA;
    for (int i = tid; i < T_DATA; i += 256) ss[T_NO - 1 + i] = sp[i];
    __syncthreads();

    for (int h = 0; h < HID_NO; h++) {
        const int c = s * HID_NO + h;
        float w[T_NO];
#pragma unroll
        for (int i = 0; i < T_NO; i++) w[i] = __ldg(&W1[c * T_NO + i]);
        float* cp = g_conv + ((size_t)(b * SH_NO + c)) * T_DATA;
        for (int t = tid; t < T_DATA; t += 256) {
            float acc = 0.0f;
#pragma unroll
            for (int tau = 0; tau < T_NO; tau++)
                acc = fmaf(ss[T_NO - 1 + t - tau], w[tau], acc);
            cp[t] = acc;
        }
    }
}

// ---------- 4. recurrence: lockstep 4-warp pipeline (proven round-5 structure) ----------
// W0(A): taps 1..19 serial; W1: 20..29 + conv; W2: 30..39 + stores; W3: 40..50.
template<int TB0, int NT, int WD, int MODE>
__device__ __forceinline__ void run_helper(
    int lane, int ch, int c,
    const float* __restrict__ Wh, const float* __restrict__ b1,
    const float* __restrict__ W2l,
    unsigned long long (*s_y)[32][7], unsigned long long (*sp)[32][7])
{
    float w[NT];
#pragma unroll
    for (int u = 0; u < NT; u++) w[u] = __ldg(&Wh[c * T_NO + TB0 + u - 1]);
    const float bias = (MODE == 1) ? b1[c] : 0.0f;
    const float ew2  = (MODE == 2) ? expf(W2l[c]) : 0.0f;
    const float* cv = g_conv + (size_t)ch * T_DATA;
    float* yo = g_ybuf + (size_t)ch * T_DATA;

    float yw[WD];
#pragma unroll
    for (int i = 0; i < WD; i++) yw[i] = 0.0f;

    float cn[10];
    // prologue: P[0]
    if (MODE == 1) {
        float c0[10];
#pragma unroll
        for (int j = 0; j < 10; j += 2) {
            float2 t = *(const float2*)(cv + j);
            c0[j] = t.x; c0[j + 1] = t.y;
        }
        float* pr = (float*)&sp[0][lane][0];
#pragma unroll
        for (int j = 0; j < 10; j++) pr[j] = c0[j] + bias;
#pragma unroll
        for (int j = 0; j < 10; j += 2) {
            float2 t = *(const float2*)(cv + PCH + j);
            cn[j] = t.x; cn[j + 1] = t.y;
        }
    } else {
        float* pr = (float*)&sp[0][lane][0];
#pragma unroll
        for (int j = 0; j < 10; j++) pr[j] = 0.0f;
    }
    __syncthreads();                       // bar 0

    // peeled k=0: P[1] (zero history)
    {
        float* pr = (float*)&sp[1][lane][0];
        if (MODE == 1) {
#pragma unroll
            for (int j = 0; j < 10; j++) pr[j] = cn[j] + bias;
#pragma unroll
            for (int j = 0; j < 10; j += 2) {
                float2 t = *(const float2*)(cv + 2 * PCH + j);
                cn[j] = t.x; cn[j + 1] = t.y;
            }
        } else {
#pragma unroll
            for (int j = 0; j < 10; j++) pr[j] = 0.0f;
        }
    }
    __syncthreads();                       // bar 1

    for (int k = 1; k <= NCHUNKS - 2; k++) {
        float yn[10];
        {
            const unsigned long long* yr = &s_y[(k - 1) & 1][lane][0];
#pragma unroll
            for (int q = 0; q < 5; q++) {
                float2 t = upk2(yr[q]);
                yn[2 * q] = t.x; yn[2 * q + 1] = t.y;
            }
        }
        if (MODE == 2) {
            float* yob = yo + (size_t)(k - 1) * PCH;
#pragma unroll
            for (int q = 0; q < 5; q++)
                *(float2*)(yob + 2 * q) =
                    make_float2(ew2 * yn[2 * q], ew2 * yn[2 * q + 1]);
        }
#pragma unroll
        for (int i = 0; i < WD - 10; i++) yw[i] = yw[i + 10];
#pragma unroll
        for (int j = 0; j < 10; j++) yw[WD - 10 + j] = yn[j];

        float part[10];
        if (MODE == 1) {
#pragma unroll
            for (int j = 0; j < 10; j++) part[j] = cn[j] + bias;
            int nidx = (k + 2 <= NCHUNKS - 1) ? (k + 2) : (NCHUNKS - 1);
#pragma unroll
            for (int j = 0; j < 10; j += 2) {
                float2 t = *(const float2*)(cv + nidx * PCH + j);
                cn[j] = t.x; cn[j + 1] = t.y;
            }
        } else {
#pragma unroll
            for (int j = 0; j < 10; j++) part[j] = 0.0f;
        }
#pragma unroll
        for (int j = 0; j < 10; j++)
#pragma unroll
            for (int u = 0; u < NT; u++)
                part[j] = fmaf(yw[WD + 10 + j - TB0 - u], w[u], part[j]);

        float* pw = (float*)&sp[(k + 1) & 1][lane][0];
#pragma unroll
        for (int j = 0; j < 10; j++) pw[j] = part[j];
        __syncthreads();                   // bars 2..499
    }

    if (MODE == 2) {
        const unsigned long long* yr = &s_y[(NCHUNKS - 2) & 1][lane][0];
        float* yob = yo + (size_t)(NCHUNKS - 2) * PCH;
#pragma unroll
        for (int q = 0; q < 5; q++) {
            float2 t = upk2(yr[q]);
            *(float2*)(yob + 2 * q) = make_float2(ew2 * t.x, ew2 * t.y);
        }
    }
    __syncthreads();                       // bar 500
    if (MODE == 2) {
        const unsigned long long* yr = &s_y[(NCHUNKS - 1) & 1][lane][0];
        float* yob = yo + (size_t)(NCHUNKS - 1) * PCH;
#pragma unroll
        for (int q = 0; q < 5; q++) {
            float2 t = upk2(yr[q]);
            *(float2*)(yob + 2 * q) = make_float2(ew2 * t.x, ew2 * t.y);
        }
    }
}

__global__ void __launch_bounds__(128, 1) recur_kernel(const float* __restrict__ Wh,
                                                       const float* __restrict__ b1,
                                                       const float* __restrict__ W2l) {
    __shared__ unsigned long long s_y[2][32][7];
    __shared__ unsigned long long s_p1[2][32][7];
    __shared__ unsigned long long s_p2[2][32][7];
    __shared__ unsigned long long s_p3[2][32][7];

    const int lane = threadIdx.x & 31;
    const int warp = threadIdx.x >> 5;
    const int ch = blockIdx.x * 32 + lane;
    const int c = ch % SH_NO;

    if (warp == 0) {
        float w[21];
#pragma unroll
        for (int i = 0; i < 19; i++) w[i] = __ldg(&Wh[c * T_NO + i]);
        w[19] = 0.0f; w[20] = 0.0f;
        unsigned long long wp0[10], wp1[10];
#pragma unroll
        for (int i = 0; i < 10; i++) {
            wp0[i] = pk2(w[2 * i], w[2 * i + 1]);
            wp1[i] = pk2(w[2 * i + 1], w[2 * i + 2]);
        }

        unsigned long long A2[15];         // rotating window, period 3
#pragma unroll
        for (int m = 0; m < 15; m++) A2[m] = 0ull;

        int k = 0;
        __syncthreads();                   // bar 0

// One chunk with compile-time window base BASE (0,5,10). Replaces the
// register shift with 5 zeroings of the just-consumed pairs.
#define ABODY(BASE)                                                          \
    {                                                                        \
        const unsigned long long* pp1 = &s_p1[k & 1][lane][0];               \
        const unsigned long long* pp2 = &s_p2[k & 1][lane][0];               \
        const unsigned long long* pp3 = &s_p3[k & 1][lane][0];               \
        _Pragma("unroll")                                                    \
        for (int m = 0; m < 5; m++)                                          \
            A2[(BASE + m) % 15] = add2(A2[(BASE + m) % 15],                  \
                add2(add2(pp1[m], pp2[m]), pp3[m]));                         \
        unsigned long long* yrow = &s_y[k & 1][lane][0];                     \
        _Pragma("unroll")                                                    \
        for (int pp = 0; pp < 5; pp++) {                                     \
            float2 a = upk2(A2[(BASE + pp) % 15]);                           \
            float y0 = tanh_hw(a.x);                                         \
            float v1 = fmaf(y0, w[0], a.y);                                  \
            float y1 = tanh_hw(v1);                                          \
            yrow[pp] = pk2(y0, y1);                                          \
            unsigned long long yy0 = pk2(y0, y0);                            \
            unsigned long long yy1 = pk2(y1, y1);                            \
            _Pragma("unroll")                                                \
            for (int i = 0; i < 10; i++)                                     \
                A2[(BASE + pp + 1 + i) % 15] =                               \
                    ffma2(yy0, wp1[i], ffma2(yy1, wp0[i],                    \
                          A2[(BASE + pp + 1 + i) % 15]));                    \
        }                                                                    \
        _Pragma("unroll")                                                    \
        for (int m = 0; m < 5; m++) A2[(BASE + m) % 15] = 0ull;              \
        __syncthreads();                                                     \
        k++;                                                                 \
    }

        for (int t3 = 0; t3 < 166; t3++) {   // 166*3 = 498 chunks
            ABODY(0)
            ABODY(5)
            ABODY(10)
        }
        ABODY(0)                             // chunk 498
        ABODY(5)                             // chunk 499
#undef ABODY
    } else if (warp == 1) {
        run_helper<20, 10, 19, 1>(lane, ch, c, Wh, b1, W2l, s_y, s_p1);
    } else if (warp == 2) {
        run_helper<30, 10, 29, 2>(lane, ch, c, Wh, b1, W2l, s_y, s_p2);
    } else {
        run_helper<40, 11, 40, 0>(lane, ch, c, Wh, b1, W2l, s_y, s_p3);
    }
}

// ---------- 5. reduce ----------
__global__ void __launch_bounds__(256) reduce_kernel(const float* __restrict__ V_o,
                                                     float* __restrict__ out) {
    int idx = blockIdx.x * 256 + threadIdx.x;
    if (idx >= B_NO * T_DATA) return;
    int b = idx / T_DATA, t = idx % T_DATA;
    const float* p = g_ybuf + (size_t)b * SH_NO * T_DATA + t;
    float a = V_o[0];
#pragma unroll 10
    for (int c = 0; c < SH_NO; c++) a += p[(size_t)c * T_DATA];
    out[idx] = a;
}

extern "C" void kernel_launch(void* const* d_in, const int* in_sizes, int n_in,
                              void* d_out, int out_size) {
    const float* S_e     = (const float*)d_in[0];
    const float* C_syn_e = (const float*)d_in[2];
    const float* E_scale = (const float*)d_in[4];
    const float* W1      = (const float*)d_in[6];
    const float* W2      = (const float*)d_in[7];
    const float* b1      = (const float*)d_in[8];
    const float* Wh      = (const float*)d_in[9];
    const float* V_o     = (const float*)d_in[11];
    float* out = (float*)d_out;

    prep_kernel<<<(E_NO * SUB_NO + 255) / 256, 256>>>(C_syn_e, E_scale);
    dim3 gg((T_DATA + GROWS - 1) / GROWS, B_NO);
    gemm_kernel<<<gg, GTHR>>>(S_e);
    conv_kernel<<<B_NO * SUB_NO, 256>>>(W1);
    recur_kernel<<<NCH / 32, 128>>>(Wh, b1, W2);
    reduce_kernel<<<(B_NO * T_DATA + 255) / 256, 256>>>(V_o, out);
}

// round 11
// speedup vs baseline: 1.1159x; 1.0306x over previous
#include <cuda_runtime.h>
#include <cstdint>

#define B_NO   8
#define T_DATA 5000
#define E_NO   2000
#define SUB_NO 20
#define HID_NO 10
#define SH_NO  200
#define T_NO   50
#define NCH    1600

#define PCH 10
#define NCHUNKS 500

// Full named-barrier sync per group (ids 1,2; 128 threads each).
// Same semantics as __syncthreads for the 4 participating warps.
#define BARG(id) asm volatile("bar.sync %0, %1;" :: "r"(id), "r"(128) : "memory")

__device__ float g_CT[E_NO * SUB_NO];
__device__ float g_syn[B_NO * SUB_NO * T_DATA];
__device__ float g_conv[B_NO * SH_NO * (size_t)T_DATA];
__device__ float g_ybuf[B_NO * SH_NO * (size_t)T_DATA];

__device__ __forceinline__ unsigned long long pk2(float x, float y) {
    unsigned long long r;
    asm("mov.b64 %0, {%1, %2};" : "=l"(r) : "f"(x), "f"(y));
    return r;
}
__device__ __forceinline__ unsigned long long ffma2(unsigned long long a,
                                                    unsigned long long b,
                                                    unsigned long long c) {
    unsigned long long d;
    asm("fma.rn.f32x2 %0, %1, %2, %3;" : "=l"(d) : "l"(a), "l"(b), "l"(c));
    return d;
}
__device__ __forceinline__ unsigned long long add2(unsigned long long a,
                                                   unsigned long long b) {
    unsigned long long d;
    asm("add.rn.f32x2 %0, %1, %2;" : "=l"(d) : "l"(a), "l"(b));
    return d;
}
__device__ __forceinline__ float2 upk2(unsigned long long v) {
    float2 f;
    asm("mov.b64 {%0, %1}, %2;" : "=f"(f.x), "=f"(f.y) : "l"(v));
    return f;
}
__device__ __forceinline__ float tanh_hw(float x) {
    float y;
    asm("tanh.approx.f32 %0, %1;" : "=f"(y) : "f"(x));
    return y;
}

// ---------- 1. prep ----------
__global__ void prep_kernel(const float* __restrict__ C, const float* __restrict__ Esc) {
    int i = blockIdx.x * 256 + threadIdx.x;
    if (i >= E_NO * SUB_NO) return;
    int e = i / SUB_NO, s = i % SUB_NO;
    g_CT[i] = C[s * E_NO + e] * expf(Esc[e]);
}

// ---------- 2. GEMM (round-5 proven version: 64 thr, 2 rows/thread) ----------
#define ETILE 16
#define GROWS 128
#define GTHR  64
#define NTILE (E_NO / ETILE)

__global__ void __launch_bounds__(GTHR) gemm_kernel(const float* __restrict__ S_e) {
    __shared__ float sS[2][GROWS * 17];
    __shared__ float sC[2][ETILE * 20];
    const int b = blockIdx.y;
    const int t0 = blockIdx.x * GROWS;
    const int tid = threadIdx.x;
    const float* Sb = S_e + (size_t)b * T_DATA * E_NO;

    unsigned long long acc0[10], acc1[10];
#pragma unroll
    for (int s = 0; s < 10; s++) { acc0[s] = 0ull; acc1[s] = 0ull; }

    float4 pf[8];
    float pc[5];

#define LDG_TILE(E0)                                                        \
    {                                                                       \
        _Pragma("unroll")                                                   \
        for (int kk = 0; kk < 8; kk++) {                                    \
            int q = tid + kk * GTHR;                                        \
            int r = q >> 2, c4 = q & 3;                                     \
            int t = t0 + r;                                                 \
            pf[kk] = (t < T_DATA)                                           \
                ? *(const float4*)(Sb + (size_t)t * E_NO + (E0) + c4 * 4)   \
                : make_float4(0.f, 0.f, 0.f, 0.f);                          \
        }                                                                   \
        _Pragma("unroll")                                                   \
        for (int m = 0; m < 5; m++) pc[m] = g_CT[(E0) * 20 + tid * 5 + m];  \
    }

#define STS_TILE(BUF)                                                       \
    {                                                                       \
        _Pragma("unroll")                                                   \
        for (int kk = 0; kk < 8; kk++) {                                    \
            int q = tid + kk * GTHR;                                        \
            int r = q >> 2, c4 = q & 3;                                     \
            float* d = &sS[BUF][r * 17 + c4 * 4];                           \
            d[0] = pf[kk].x; d[1] = pf[kk].y;                               \
            d[2] = pf[kk].z; d[3] = pf[kk].w;                               \
        }                                                                   \
        _Pragma("unroll")                                                   \
        for (int m = 0; m < 5; m++) sC[BUF][tid * 5 + m] = pc[m];           \
    }

    LDG_TILE(0);
    STS_TILE(0);
    LDG_TILE(ETILE);
    __syncthreads();

    for (int it = 0; it < NTILE; it++) {
        const int cur = it & 1;
#pragma unroll
        for (int j = 0; j < ETILE; j++) {
            unsigned long long cp[10];
#pragma unroll
            for (int s = 0; s < 10; s++)
                cp[s] = *(const unsigned long long*)&sC[cur][j * 20 + 2 * s];
            float v0 = sS[cur][tid * 17 + j];
            float v1 = sS[cur][(tid + GTHR) * 17 + j];
            unsigned long long v0p = pk2(v0, v0), v1p = pk2(v1, v1);
#pragma unroll
            for (int s = 0; s < 10; s++) {
                acc0[s] = ffma2(v0p, cp[s], acc0[s]);
                acc1[s] = ffma2(v1p, cp[s], acc1[s]);
            }
        }
        if (it < NTILE - 1) {
            STS_TILE(cur ^ 1);
            if (it < NTILE - 2) LDG_TILE((it + 2) * ETILE);
            __syncthreads();
        }
    }

    int ta = t0 + tid;
    if (ta < T_DATA) {
#pragma unroll
        for (int s = 0; s < 10; s++) {
            float2 f = upk2(acc0[s]);
            g_syn[((size_t)b * SUB_NO + 2 * s)     * T_DATA + ta] = f.x;
            g_syn[((size_t)b * SUB_NO + 2 * s + 1) * T_DATA + ta] = f.y;
        }
    }
    int tb = t0 + GTHR + tid;
    if (tb < T_DATA) {
#pragma unroll
        for (int s = 0; s < 10; s++) {
            float2 f = upk2(acc1[s]);
            g_syn[((size_t)b * SUB_NO + 2 * s)     * T_DATA + tb] = f.x;
            g_syn[((size_t)b * SUB_NO + 2 * s + 1) * T_DATA + tb] = f.y;
        }
    }
}

// ---------- 3. depthwise causal conv ----------
__global__ void __launch_bounds__(256) conv_kernel(const float* __restrict__ W1) {
    const int bs = blockIdx.x;
    const int b = bs / SUB_NO, s = bs % SUB_NO;
    __shared__ float ss[T_NO - 1 + T_DATA];
    const int tid = threadIdx.x;

    for (int i = tid; i < T_NO - 1; i += 256) ss[i] = 0.0f;
    const float* sp = g_syn + ((size_t)b * SUB_NO + s) * T_DATA;
    for (int i = tid; i < T_DATA; i += 256) ss[T_NO - 1 + i] = sp[i];
    __syncthreads();

    for (int h = 0; h < HID_NO; h++) {
        const int c = s * HID_NO + h;
        float w[T_NO];
#pragma unroll
        for (int i = 0; i < T_NO; i++) w[i] = __ldg(&W1[c * T_NO + i]);
        float* cp = g_conv + ((size_t)(b * SH_NO + c)) * T_DATA;
        for (int t = tid; t < T_DATA; t += 256) {
            float acc = 0.0f;
#pragma unroll
            for (int tau = 0; tau < T_NO; tau++)
                acc = fmaf(ss[T_NO - 1 + t - tau], w[tau], acc);
            cp[t] = acc;
        }
    }
}

// ---------- 4. recurrence: TWO independent 4-warp pipelines per block ----------
// 8 warps = 2 groups; group g = 4 roles on the 4 SMSPs; stalls of one group are
// filled by the other group's warp on the same SMSP.
// Role 0 (A): taps 1..19 serial; role 1: 20..29 + conv; role 2: 30..39 + stores;
// role 3: 40..50.
template<int TB0, int NT, int WD, int MODE>
__device__ __forceinline__ void run_helper(
    int lane, int ch, int c, int bid,
    const float* __restrict__ Wh, const float* __restrict__ b1,
    const float* __restrict__ W2l,
    unsigned long long (*s_y)[32][7], unsigned long long (*sp)[32][7])
{
    float w[NT];
#pragma unroll
    for (int u = 0; u < NT; u++) w[u] = __ldg(&Wh[c * T_NO + TB0 + u - 1]);
    const float bias = (MODE == 1) ? b1[c] : 0.0f;
    const float ew2  = (MODE == 2) ? expf(W2l[c]) : 0.0f;
    const float* cv = g_conv + (size_t)ch * T_DATA;
    float* yo = g_ybuf + (size_t)ch * T_DATA;

    float yw[WD];
#pragma unroll
    for (int i = 0; i < WD; i++) yw[i] = 0.0f;

    float cn[10];
    // prologue: P[0]
    if (MODE == 1) {
        float c0[10];
#pragma unroll
        for (int j = 0; j < 10; j += 2) {
            float2 t = *(const float2*)(cv + j);
            c0[j] = t.x; c0[j + 1] = t.y;
        }
        float* pr = (float*)&sp[0][lane][0];
#pragma unroll
        for (int j = 0; j < 10; j++) pr[j] = c0[j] + bias;
#pragma unroll
        for (int j = 0; j < 10; j += 2) {
            float2 t = *(const float2*)(cv + PCH + j);
            cn[j] = t.x; cn[j + 1] = t.y;
        }
    } else {
        float* pr = (float*)&sp[0][lane][0];
#pragma unroll
        for (int j = 0; j < 10; j++) pr[j] = 0.0f;
    }
    BARG(bid);                             // bar 0

    // peeled k=0: P[1] (zero history)
    {
        float* pr = (float*)&sp[1][lane][0];
        if (MODE == 1) {
#pragma unroll
            for (int j = 0; j < 10; j++) pr[j] = cn[j] + bias;
#pragma unroll
            for (int j = 0; j < 10; j += 2) {
                float2 t = *(const float2*)(cv + 2 * PCH + j);
                cn[j] = t.x; cn[j + 1] = t.y;
            }
        } else {
#pragma unroll
            for (int j = 0; j < 10; j++) pr[j] = 0.0f;
        }
    }
    BARG(bid);                             // bar 1

    for (int k = 1; k <= NCHUNKS - 2; k++) {
        float yn[10];
        {
            const unsigned long long* yr = &s_y[(k - 1) & 1][lane][0];
#pragma unroll
            for (int q = 0; q < 5; q++) {
                float2 t = upk2(yr[q]);
                yn[2 * q] = t.x; yn[2 * q + 1] = t.y;
            }
        }
        if (MODE == 2) {
            float* yob = yo + (size_t)(k - 1) * PCH;
#pragma unroll
            for (int q = 0; q < 5; q++)
                *(float2*)(yob + 2 * q) =
                    make_float2(ew2 * yn[2 * q], ew2 * yn[2 * q + 1]);
        }
#pragma unroll
        for (int i = 0; i < WD - 10; i++) yw[i] = yw[i + 10];
#pragma unroll
        for (int j = 0; j < 10; j++) yw[WD - 10 + j] = yn[j];

        float part[10];
        if (MODE == 1) {
#pragma unroll
            for (int j = 0; j < 10; j++) part[j] = cn[j] + bias;
            int nidx = (k + 2 <= NCHUNKS - 1) ? (k + 2) : (NCHUNKS - 1);
#pragma unroll
            for (int j = 0; j < 10; j += 2) {
                float2 t = *(const float2*)(cv + nidx * PCH + j);
                cn[j] = t.x; cn[j + 1] = t.y;
            }
        } else {
#pragma unroll
            for (int j = 0; j < 10; j++) part[j] = 0.0f;
        }
#pragma unroll
        for (int j = 0; j < 10; j++)
#pragma unroll
            for (int u = 0; u < NT; u++)
                part[j] = fmaf(yw[WD + 10 + j - TB0 - u], w[u], part[j]);

        float* pw = (float*)&sp[(k + 1) & 1][lane][0];
#pragma unroll
        for (int j = 0; j < 10; j++) pw[j] = part[j];
        BARG(bid);                         // bars 2..499
    }

    if (MODE == 2) {
        const unsigned long long* yr = &s_y[(NCHUNKS - 2) & 1][lane][0];
        float* yob = yo + (size_t)(NCHUNKS - 2) * PCH;
#pragma unroll
        for (int q = 0; q < 5; q++) {
            float2 t = upk2(yr[q]);
            *(float2*)(yob + 2 * q) = make_float2(ew2 * t.x, ew2 * t.y);
        }
    }
    BARG(bid);                             // bar 500
    if (MODE == 2) {
        const unsigned long long* yr = &s_y[(NCHUNKS - 1) & 1][lane][0];
        float* yob = yo + (size_t)(NCHUNKS - 1) * PCH;
#pragma unroll
        for (int q = 0; q < 5; q++) {
            float2 t = upk2(yr[q]);
            *(float2*)(yob + 2 * q) = make_float2(ew2 * t.x, ew2 * t.y);
        }
    }
}

__global__ void __launch_bounds__(256, 1) recur_kernel(const float* __restrict__ Wh,
                                                       const float* __restrict__ b1,
                                                       const float* __restrict__ W2l) {
    __shared__ unsigned long long s_y[2][2][32][7];
    __shared__ unsigned long long s_p1[2][2][32][7];
    __shared__ unsigned long long s_p2[2][2][32][7];
    __shared__ unsigned long long s_p3[2][2][32][7];

    const int lane = threadIdx.x & 31;
    const int wid = threadIdx.x >> 5;           // 0..7
    const int grp = wid >> 2;                   // 0,1
    const int role = (wid < 4) ? wid : (7 - wid); // balance SMSP pairing
    const int bid = 1 + grp;                    // named barrier id
    const int ch = blockIdx.x * 64 + grp * 32 + lane;
    const int c = ch % SH_NO;

    if (role == 0) {
        float w[21];
#pragma unroll
        for (int i = 0; i < 19; i++) w[i] = __ldg(&Wh[c * T_NO + i]);
        w[19] = 0.0f; w[20] = 0.0f;
        unsigned long long wp0[10], wp1[10];
#pragma unroll
        for (int i = 0; i < 10; i++) {
            wp0[i] = pk2(w[2 * i], w[2 * i + 1]);
            wp1[i] = pk2(w[2 * i + 1], w[2 * i + 2]);
        }

        unsigned long long A2[15];              // rotating window, period 3
#pragma unroll
        for (int m = 0; m < 15; m++) A2[m] = 0ull;

        int k = 0;
        BARG(bid);                              // bar 0

#define ABODY(BASE)                                                          \
    {                                                                        \
        const unsigned long long* pp1 = &s_p1[grp][k & 1][lane][0];          \
        const unsigned long long* pp2 = &s_p2[grp][k & 1][lane][0];          \
        const unsigned long long* pp3 = &s_p3[grp][k & 1][lane][0];          \
        _Pragma("unroll")                                                    \
        for (int m = 0; m < 5; m++)                                          \
            A2[(BASE + m) % 15] = add2(A2[(BASE + m) % 15],                  \
                add2(add2(pp1[m], pp2[m]), pp3[m]));                         \
        unsigned long long* yrow = &s_y[grp][k & 1][lane][0];                \
        _Pragma("unroll")                                                    \
        for (int pp = 0; pp < 5; pp++) {                                     \
            float2 a = upk2(A2[(BASE + pp) % 15]);                           \
            float y0 = tanh_hw(a.x);                                         \
            float v1 = fmaf(y0, w[0], a.y);                                  \
            float y1 = tanh_hw(v1);                                          \
            yrow[pp] = pk2(y0, y1);                                          \
            unsigned long long yy0 = pk2(y0, y0);                            \
            unsigned long long yy1 = pk2(y1, y1);                            \
            _Pragma("unroll")                                                \
            for (int i = 0; i < 10; i++)                                     \
                A2[(BASE + pp + 1 + i) % 15] =                               \
                    ffma2(yy0, wp1[i], ffma2(yy1, wp0[i],                    \
                          A2[(BASE + pp + 1 + i) % 15]));                    \
        }                                                                    \
        _Pragma("unroll")                                                    \
        for (int m = 0; m < 5; m++) A2[(BASE + m) % 15] = 0ull;              \
        BARG(bid);                                                           \
        k++;                                                                 \
    }

        for (int t3 = 0; t3 < 166; t3++) {      // 498 chunks
            ABODY(0)
            ABODY(5)
            ABODY(10)
        }
        ABODY(0)                                // chunk 498
        ABODY(5)                                // chunk 499
#undef ABODY
    } else if (role == 1) {
        run_helper<20, 10, 19, 1>(lane, ch, c, bid, Wh, b1, W2l, s_y[grp], s_p1[grp]);
    } else if (role == 2) {
        run_helper<30, 10, 29, 2>(lane, ch, c, bid, Wh, b1, W2l, s_y[grp], s_p2[grp]);
    } else {
        run_helper<40, 11, 40, 0>(lane, ch, c, bid, Wh, b1, W2l, s_y[grp], s_p3[grp]);
    }
}

// ---------- 5. reduce ----------
__global__ void __launch_bounds__(256) reduce_kernel(const float* __restrict__ V_o,
                                                     float* __restrict__ out) {
    int idx = blockIdx.x * 256 + threadIdx.x;
    if (idx >= B_NO * T_DATA) return;
    int b = idx / T_DATA, t = idx % T_DATA;
    const float* p = g_ybuf + (size_t)b * SH_NO * T_DATA + t;
    float a = V_o[0];
#pragma unroll 10
    for (int c = 0; c < SH_NO; c++) a += p[(size_t)c * T_DATA];
    out[idx] = a;
}

extern "C" void kernel_launch(void* const* d_in, const int* in_sizes, int n_in,
                              void* d_out, int out_size) {
    const float* S_e     = (const float*)d_in[0];
    const float* C_syn_e = (const float*)d_in[2];
    const float* E_scale = (const float*)d_in[4];
    const float* W1      = (const float*)d_in[6];
    const float* W2      = (const float*)d_in[7];
    const float* b1      = (const float*)d_in[8];
    const float* Wh      = (const float*)d_in[9];
    const float* V_o     = (const float*)d_in[11];
    float* out = (float*)d_out;

    prep_kernel<<<(E_NO * SUB_NO + 255) / 256, 256>>>(C_syn_e, E_scale);
    dim3 gg((T_DATA + GROWS - 1) / GROWS, B_NO);
    gemm_kernel<<<gg, GTHR>>>(S_e);
    conv_kernel<<<B_NO * SUB_NO, 256>>>(W1);
    recur_kernel<<<NCH / 64, 256>>>(Wh, b1, W2);
    reduce_kernel<<<(B_NO * T_DATA + 255) / 256, 256>>>(V_o, out);
}